// round 1
// baseline (speedup 1.0000x reference)
#include <cuda_runtime.h>
#include <math.h>

#define N_NODES 6144
#define NFEAT   128
#define HID     128
#define NHEADS  8
#define NCLASS  40
#define MAXD    64
#define EPS     1e-5f
#define ALPHA   0.2f
#define FULL    0xffffffffu

// ---------------- scratch (static device globals; no dynamic alloc) -------
__device__ float g_xn[N_NODES * NFEAT];                 // bn0(x)
__device__ float g_Wh[NHEADS * N_NODES * HID];          // per-head projections
__device__ float g_s1[NHEADS * N_NODES];
__device__ float g_s2[NHEADS * N_NODES];
__device__ int   g_col[N_NODES * MAXD];
__device__ float g_val[N_NODES * MAXD];
__device__ int   g_cnt[N_NODES];
__device__ float g_xcat[N_NODES * NHEADS * HID];        // concat of head outputs
__device__ float g_sup[N_NODES * NCLASS];               // xcat @ gc_w

// ---------------- K1: bn0 --------------------------------------------------
__global__ void k_bn0(const float* __restrict__ x,
                      const float* __restrict__ g, const float* __restrict__ b,
                      const float* __restrict__ m, const float* __restrict__ v) {
    int idx = blockIdx.x * blockDim.x + threadIdx.x;
    if (idx >= N_NODES * NFEAT) return;
    int f = idx & (NFEAT - 1);
    float sc = g[f] / sqrtf(v[f] + EPS);
    g_xn[idx] = (x[idx] - m[f]) * sc + b[f];
}

// ---------------- K2: Wh[h] = xn @ W_att[h]  (64x128 tile, KC=32) ----------
__global__ void k_wh_gemm(const float* __restrict__ Watt) {
    __shared__ float As[64][33];
    __shared__ float Bs[32][128];
    int h = blockIdx.y;
    int nodeBase = blockIdx.x * 64;
    int tid = threadIdx.x;
    int tx = tid & 15;    // col group: 8 outputs
    int ty = tid >> 4;    // row group: 4 nodes
    const float* Bsrc = Watt + h * NFEAT * HID;
    float acc[4][8];
#pragma unroll
    for (int r = 0; r < 4; ++r)
#pragma unroll
        for (int c = 0; c < 8; ++c) acc[r][c] = 0.f;

    for (int kc = 0; kc < NFEAT; kc += 32) {
        // load A tile 64x32 (scalar, coalesced)
#pragma unroll
        for (int f = tid; f < 64 * 32; f += 256) {
            int r = f >> 5, c = f & 31;
            As[r][c] = g_xn[(nodeBase + r) * NFEAT + kc + c];
        }
        // load B tile 32x128 (float4, coalesced)
#pragma unroll
        for (int rr = 0; rr < 4; ++rr) {
            int f4 = tid + 256 * rr;           // 1024 float4 total
            int r = f4 >> 5, c = (f4 & 31) << 2;
            *(float4*)&Bs[r][c] = *(const float4*)&Bsrc[(kc + r) * HID + c];
        }
        __syncthreads();
#pragma unroll
        for (int k = 0; k < 32; ++k) {
            float a0 = As[ty * 4 + 0][k];
            float a1 = As[ty * 4 + 1][k];
            float a2 = As[ty * 4 + 2][k];
            float a3 = As[ty * 4 + 3][k];
            float4 b0 = *(float4*)&Bs[k][tx * 8];
            float4 b1 = *(float4*)&Bs[k][tx * 8 + 4];
            float bb[8] = {b0.x, b0.y, b0.z, b0.w, b1.x, b1.y, b1.z, b1.w};
#pragma unroll
            for (int c = 0; c < 8; ++c) {
                acc[0][c] += a0 * bb[c];
                acc[1][c] += a1 * bb[c];
                acc[2][c] += a2 * bb[c];
                acc[3][c] += a3 * bb[c];
            }
        }
        __syncthreads();
    }
#pragma unroll
    for (int r = 0; r < 4; ++r) {
        int node = nodeBase + ty * 4 + r;
        float4 o0 = {acc[r][0], acc[r][1], acc[r][2], acc[r][3]};
        float4 o1 = {acc[r][4], acc[r][5], acc[r][6], acc[r][7]};
        *(float4*)&g_Wh[((size_t)h * N_NODES + node) * HID + tx * 8]     = o0;
        *(float4*)&g_Wh[((size_t)h * N_NODES + node) * HID + tx * 8 + 4] = o1;
    }
}

// ---------------- K3: s1/s2 = Wh @ a_src/a_dst  (warp per (h,i)) -----------
__global__ void k_scores(const float* __restrict__ asrc, const float* __restrict__ adst) {
    int wid = (blockIdx.x * blockDim.x + threadIdx.x) >> 5;
    int lane = threadIdx.x & 31;
    if (wid >= NHEADS * N_NODES) return;
    int h = wid / N_NODES;
    int i = wid - h * N_NODES;
    const float* row = &g_Wh[((size_t)h * N_NODES + i) * HID];
    float a1 = 0.f, a2 = 0.f;
#pragma unroll
    for (int t = 0; t < 4; ++t) {
        int k = lane + t * 32;
        float v = row[k];
        a1 += v * asrc[h * HID + k];
        a2 += v * adst[h * HID + k];
    }
#pragma unroll
    for (int off = 16; off; off >>= 1) {
        a1 += __shfl_xor_sync(FULL, a1, off);
        a2 += __shfl_xor_sync(FULL, a2, off);
    }
    if (lane == 0) { g_s1[wid] = a1; g_s2[wid] = a2; }
}

// ---------------- K4: CSR build (warp per row, ordered ballot compaction) --
__global__ void k_csr(const float* __restrict__ adj) {
    int row = (blockIdx.x * blockDim.x + threadIdx.x) >> 5;
    int lane = threadIdx.x & 31;
    if (row >= N_NODES) return;
    const float* arow = adj + (size_t)row * N_NODES;
    int cnt = 0;
    for (int base = 0; base < N_NODES; base += 32) {
        float v = arow[base + lane];
        bool nz = v > 0.f;
        unsigned msk = __ballot_sync(FULL, nz);
        int pos = cnt + __popc(msk & ((1u << lane) - 1u));
        if (nz && pos < MAXD) {
            g_col[row * MAXD + pos] = base + lane;
            g_val[row * MAXD + pos] = v;
        }
        cnt += __popc(msk);
    }
    if (lane == 0) g_cnt[row] = cnt < MAXD ? cnt : MAXD;
}

// ---------------- K5: sparse attention softmax + aggregate + bn1 + relu ----
// block = 256 threads = 8 warps; warp w handles head w for node blockIdx.x
__global__ void k_attn(const float* __restrict__ g1, const float* __restrict__ b1,
                       const float* __restrict__ m1, const float* __restrict__ v1) {
    int i = blockIdx.x;
    int h = threadIdx.x >> 5;
    int lane = threadIdx.x & 31;
    int cnt = g_cnt[i];
    float s1i = g_s1[h * N_NODES + i];

    int   c0 = 0, c1 = 0;
    float e0 = -INFINITY, e1 = -INFINITY;
    if (lane < cnt) {
        c0 = g_col[i * MAXD + lane];
        float e = s1i + g_s2[h * N_NODES + c0];
        e0 = (e > 0.f) ? e : ALPHA * e;
    }
    if (lane + 32 < cnt) {
        c1 = g_col[i * MAXD + lane + 32];
        float e = s1i + g_s2[h * N_NODES + c1];
        e1 = (e > 0.f) ? e : ALPHA * e;
    }
    float mx = fmaxf(e0, e1);
#pragma unroll
    for (int off = 16; off; off >>= 1) mx = fmaxf(mx, __shfl_xor_sync(FULL, mx, off));
    float p0 = (lane < cnt)      ? __expf(e0 - mx) : 0.f;
    float p1 = (lane + 32 < cnt) ? __expf(e1 - mx) : 0.f;
    float den = p0 + p1;
#pragma unroll
    for (int off = 16; off; off >>= 1) den += __shfl_xor_sync(FULL, den, off);
    float inv = 1.f / fmaxf(den, 1e-30f);
    float w0 = p0 * inv, w1 = p1 * inv;

    // aggregate: each lane owns features lane*4 .. lane*4+3
    float4 acc = {0.f, 0.f, 0.f, 0.f};
    for (int jj = 0; jj < cnt; ++jj) {
        int src = jj & 31;
        float wj;
        int   cj;
        if (jj < 32) { wj = __shfl_sync(FULL, w0, src); cj = __shfl_sync(FULL, c0, src); }
        else         { wj = __shfl_sync(FULL, w1, src); cj = __shfl_sync(FULL, c1, src); }
        float4 v = *(const float4*)&g_Wh[((size_t)h * N_NODES + cj) * HID + lane * 4];
        acc.x += wj * v.x; acc.y += wj * v.y; acc.z += wj * v.z; acc.w += wj * v.w;
    }
    // bn1 + relu + write into xcat
    float o[4] = {acc.x, acc.y, acc.z, acc.w};
#pragma unroll
    for (int t = 0; t < 4; ++t) {
        int f = lane * 4 + t;
        float sc = g1[f] / sqrtf(v1[f] + EPS);
        float val = (o[t] - m1[f]) * sc + b1[f];
        o[t] = val > 0.f ? val : 0.f;
    }
    float4 ov = {o[0], o[1], o[2], o[3]};
    *(float4*)&g_xcat[(size_t)i * (NHEADS * HID) + h * HID + lane * 4] = ov;
}

// ---------------- K6: support = xcat @ gc_w  (64 nodes x 40 classes) -------
__global__ void k_support(const float* __restrict__ gcw) {
    __shared__ float As[64][65];
    __shared__ float Bs[64][40];
    int tid = threadIdx.x;
    int row = tid & 63;
    int cg = tid >> 6;                 // 4 groups of 10 classes
    int nodeBase = blockIdx.x * 64;
    float acc[10];
#pragma unroll
    for (int c = 0; c < 10; ++c) acc[c] = 0.f;

    for (int kc = 0; kc < NHEADS * HID; kc += 64) {
        for (int f = tid; f < 64 * 64; f += 256) {
            int r = f >> 6, c = f & 63;
            As[r][c] = g_xcat[(size_t)(nodeBase + r) * (NHEADS * HID) + kc + c];
        }
        for (int f = tid; f < 64 * 40; f += 256) {
            int r = f / 40, c = f - r * 40;
            Bs[r][c] = gcw[(kc + r) * NCLASS + c];
        }
        __syncthreads();
#pragma unroll 8
        for (int k = 0; k < 64; ++k) {
            float a = As[row][k];
#pragma unroll
            for (int c = 0; c < 10; ++c) acc[c] += a * Bs[k][cg * 10 + c];
        }
        __syncthreads();
    }
#pragma unroll
    for (int c = 0; c < 10; ++c)
        g_sup[(size_t)(nodeBase + row) * NCLASS + cg * 10 + c] = acc[c];
}

// ---------------- K7: residual smooth + bias + log_softmax -----------------
__global__ void k_final(const float* __restrict__ gcb, float* __restrict__ out) {
    __shared__ float sm[NCLASS];
    __shared__ float red[2];
    int i = blockIdx.x;
    int c = threadIdx.x;
    if (c < NCLASS) {
        float s = g_sup[(size_t)i * NCLASS + c];
        float acc = 0.f;
        int cnt = g_cnt[i];
        for (int jj = 0; jj < cnt; ++jj)
            acc += g_val[i * MAXD + jj] * g_sup[(size_t)g_col[i * MAXD + jj] * NCLASS + c];
        sm[c] = (0.5f * acc + s) * (1.f / 1.5f) + gcb[c];
    }
    __syncthreads();
    if (c == 0) {
        float mx = -INFINITY;
        for (int k = 0; k < NCLASS; ++k) mx = fmaxf(mx, sm[k]);
        float s = 0.f;
        for (int k = 0; k < NCLASS; ++k) s += __expf(sm[k] - mx);
        red[0] = mx; red[1] = logf(s);
    }
    __syncthreads();
    if (c < NCLASS) out[(size_t)i * NCLASS + c] = sm[c] - red[0] - red[1];
}

// ---------------- launch ----------------------------------------------------
extern "C" void kernel_launch(void* const* d_in, const int* in_sizes, int n_in,
                              void* d_out, int out_size) {
    const float* x     = (const float*)d_in[0];
    const float* adj   = (const float*)d_in[1];
    const float* Watt  = (const float*)d_in[2];
    const float* asrc  = (const float*)d_in[3];
    const float* adst  = (const float*)d_in[4];
    const float* bn0g  = (const float*)d_in[5];
    const float* bn0b  = (const float*)d_in[6];
    const float* bn0m  = (const float*)d_in[7];
    const float* bn0v  = (const float*)d_in[8];
    const float* bn1g  = (const float*)d_in[9];
    const float* bn1b  = (const float*)d_in[10];
    const float* bn1m  = (const float*)d_in[11];
    const float* bn1v  = (const float*)d_in[12];
    const float* gcw   = (const float*)d_in[13];
    const float* gcb   = (const float*)d_in[14];
    float* out = (float*)d_out;

    k_bn0<<<(N_NODES * NFEAT) / 256, 256>>>(x, bn0g, bn0b, bn0m, bn0v);
    k_csr<<<N_NODES / 8, 256>>>(adj);                 // independent of bn0
    k_wh_gemm<<<dim3(N_NODES / 64, NHEADS), 256>>>(Watt);
    k_scores<<<(NHEADS * N_NODES) / 8, 256>>>(asrc, adst);
    k_attn<<<N_NODES, 256>>>(bn1g, bn1b, bn1m, bn1v);
    k_support<<<N_NODES / 64, 256>>>(gcw);
    k_final<<<N_NODES, 64>>>(gcb, out);
}

// round 2
// speedup vs baseline: 1.1848x; 1.1848x over previous
#include <cuda_runtime.h>
#include <math.h>

#define N_NODES 6144
#define NFEAT   128
#define HID     128
#define NHEADS  8
#define NCLASS  40
#define MAXD    64
#define EPS     1e-5f
#define ALPHA   0.2f
#define FULL    0xffffffffu

// ---------------- scratch -------------------------------------------------
__device__ float g_Wh[NHEADS * N_NODES * HID];
__device__ float g_s1[NHEADS * N_NODES];
__device__ float g_s2[NHEADS * N_NODES];
__device__ int   g_col[N_NODES * MAXD];
__device__ float g_val[N_NODES * MAXD];
__device__ int   g_cnt[N_NODES];
__device__ float g_xcat[N_NODES * NHEADS * HID];
__device__ float g_sup[N_NODES * NCLASS];

// ---------------- packed f32x2 helpers ------------------------------------
__device__ __forceinline__ unsigned long long pk2(float lo, float hi) {
    unsigned long long r;
    asm("mov.b64 %0, {%1,%2};" : "=l"(r) : "f"(lo), "f"(hi));
    return r;
}
__device__ __forceinline__ void upk2(unsigned long long v, float& lo, float& hi) {
    asm("mov.b64 {%0,%1}, %2;" : "=f"(lo), "=f"(hi) : "l"(v));
}
__device__ __forceinline__ void ffma2(unsigned long long& d,
                                      unsigned long long a, unsigned long long b) {
    asm("fma.rn.f32x2 %0, %1, %2, %0;" : "+l"(d) : "l"(a), "l"(b));
}

// ---------------- K1: fused bn0 + Wh GEMM + score epilogue -----------------
// 128x128 tile per block (blockIdx.x = node tile, blockIdx.y = head), 256 thr
__global__ __launch_bounds__(256) void k_wh(
    const float* __restrict__ x, const float* __restrict__ Watt,
    const float* __restrict__ asrc, const float* __restrict__ adst,
    const float* __restrict__ bg, const float* __restrict__ bb,
    const float* __restrict__ bm, const float* __restrict__ bv) {
    __shared__ float As[16][132];     // A transposed: As[k][node]
    __shared__ float Bs[16][128];
    __shared__ float s_sc[128], s_sh[128];
    int h = blockIdx.y;
    int nb = blockIdx.x * 128;
    int tid = threadIdx.x;
    int tc = tid & 15, tr = tid >> 4;

    if (tid < 128) {
        float s = bg[tid] * rsqrtf(bv[tid] + EPS);
        s_sc[tid] = s;
        s_sh[tid] = bb[tid] - bm[tid] * s;
    }
    unsigned long long acc[8][4];
#pragma unroll
    for (int r = 0; r < 8; ++r)
#pragma unroll
        for (int c = 0; c < 4; ++c) acc[r][c] = 0ull;
    __syncthreads();

    const float* Bg = Watt + (size_t)h * NFEAT * HID;
    for (int kc = 0; kc < NFEAT; kc += 16) {
        // A tile: 128 nodes x 16 feats, bn0 fused, stored transposed
#pragma unroll
        for (int l = 0; l < 2; ++l) {
            int f4 = tid + 256 * l;
            int r = f4 >> 2, cg = (f4 & 3) * 4;
            float4 v = *(const float4*)&x[(size_t)(nb + r) * NFEAT + kc + cg];
            As[cg + 0][r] = v.x * s_sc[kc + cg + 0] + s_sh[kc + cg + 0];
            As[cg + 1][r] = v.y * s_sc[kc + cg + 1] + s_sh[kc + cg + 1];
            As[cg + 2][r] = v.z * s_sc[kc + cg + 2] + s_sh[kc + cg + 2];
            As[cg + 3][r] = v.w * s_sc[kc + cg + 3] + s_sh[kc + cg + 3];
        }
        // B tile: 16 x 128
#pragma unroll
        for (int l = 0; l < 2; ++l) {
            int f4 = tid + 256 * l;
            int r = f4 >> 5, c = (f4 & 31) * 4;
            *(float4*)&Bs[r][c] = *(const float4*)&Bg[(size_t)(kc + r) * HID + c];
        }
        __syncthreads();
#pragma unroll
        for (int k = 0; k < 16; ++k) {
            float4 a0 = *(float4*)&As[k][tr * 8];
            float4 a1 = *(float4*)&As[k][tr * 8 + 4];
            float4 bv0 = *(float4*)&Bs[k][tc * 8];
            float4 bv1 = *(float4*)&Bs[k][tc * 8 + 4];
            unsigned long long bp[4] = {pk2(bv0.x, bv0.y), pk2(bv0.z, bv0.w),
                                        pk2(bv1.x, bv1.y), pk2(bv1.z, bv1.w)};
            float ar[8] = {a0.x, a0.y, a0.z, a0.w, a1.x, a1.y, a1.z, a1.w};
#pragma unroll
            for (int r = 0; r < 8; ++r) {
                unsigned long long ap = pk2(ar[r], ar[r]);
#pragma unroll
                for (int c = 0; c < 4; ++c) ffma2(acc[r][c], ap, bp[c]);
            }
        }
        __syncthreads();
    }

    // unpack
    float accf[8][8];
#pragma unroll
    for (int r = 0; r < 8; ++r)
#pragma unroll
        for (int c = 0; c < 4; ++c) upk2(acc[r][c], accf[r][2 * c], accf[r][2 * c + 1]);

    // write Wh
#pragma unroll
    for (int r = 0; r < 8; ++r) {
        int node = nb + tr * 8 + r;
        float4 o0 = {accf[r][0], accf[r][1], accf[r][2], accf[r][3]};
        float4 o1 = {accf[r][4], accf[r][5], accf[r][6], accf[r][7]};
        *(float4*)&g_Wh[((size_t)h * N_NODES + node) * HID + tc * 8]     = o0;
        *(float4*)&g_Wh[((size_t)h * N_NODES + node) * HID + tc * 8 + 4] = o1;
    }

    // fused scores: s1 = Wh @ asrc, s2 = Wh @ adst
    float av1[8], av2[8];
#pragma unroll
    for (int c = 0; c < 8; ++c) {
        av1[c] = asrc[h * HID + tc * 8 + c];
        av2[c] = adst[h * HID + tc * 8 + c];
    }
#pragma unroll
    for (int r = 0; r < 8; ++r) {
        float p1 = 0.f, p2 = 0.f;
#pragma unroll
        for (int c = 0; c < 8; ++c) { p1 += accf[r][c] * av1[c]; p2 += accf[r][c] * av2[c]; }
#pragma unroll
        for (int off = 8; off; off >>= 1) {
            p1 += __shfl_xor_sync(FULL, p1, off);
            p2 += __shfl_xor_sync(FULL, p2, off);
        }
        if (tc == 0) {
            int node = nb + tr * 8 + r;
            g_s1[h * N_NODES + node] = p1;
            g_s2[h * N_NODES + node] = p2;
        }
    }
}

// ---------------- K2: CSR build (warp/row, float4 loads) -------------------
__global__ void k_csr(const float* __restrict__ adj) {
    int row = (blockIdx.x * blockDim.x + threadIdx.x) >> 5;
    int lane = threadIdx.x & 31;
    if (row >= N_NODES) return;
    const float4* arow = (const float4*)(adj + (size_t)row * N_NODES);
    unsigned lt = (1u << lane) - 1u;
    int cnt = 0;
    for (int base = 0; base < N_NODES / 4; base += 32) {
        float4 v = arow[base + lane];
        float e[4] = {v.x, v.y, v.z, v.w};
#pragma unroll
        for (int j = 0; j < 4; ++j) {
            bool nz = e[j] > 0.f;
            unsigned msk = __ballot_sync(FULL, nz);
            int pos = cnt + __popc(msk & lt);
            if (nz && pos < MAXD) {
                g_col[row * MAXD + pos] = (base + lane) * 4 + j;
                g_val[row * MAXD + pos] = e[j];
            }
            cnt += __popc(msk);
        }
    }
    if (lane == 0) g_cnt[row] = cnt < MAXD ? cnt : MAXD;
}

// ---------------- K3: sparse attn softmax + aggregate + bn1 + relu ---------
__global__ __launch_bounds__(256) void k_attn(
    const float* __restrict__ g1, const float* __restrict__ b1,
    const float* __restrict__ m1, const float* __restrict__ v1) {
    __shared__ float sw[NHEADS][MAXD];
    __shared__ int   scn[NHEADS][MAXD];
    int i = blockIdx.x;
    int h = threadIdx.x >> 5;
    int lane = threadIdx.x & 31;
    int cnt = g_cnt[i];
    float s1i = g_s1[h * N_NODES + i];

    int   c0 = i, c1 = i;
    float e0 = -INFINITY, e1 = -INFINITY;
    if (lane < cnt) {
        c0 = g_col[i * MAXD + lane];
        float e = s1i + g_s2[h * N_NODES + c0];
        e0 = (e > 0.f) ? e : ALPHA * e;
    }
    if (lane + 32 < cnt) {
        c1 = g_col[i * MAXD + lane + 32];
        float e = s1i + g_s2[h * N_NODES + c1];
        e1 = (e > 0.f) ? e : ALPHA * e;
    }
    float mx = fmaxf(e0, e1);
#pragma unroll
    for (int off = 16; off; off >>= 1) mx = fmaxf(mx, __shfl_xor_sync(FULL, mx, off));
    float p0 = (lane < cnt)      ? __expf(e0 - mx) : 0.f;
    float p1 = (lane + 32 < cnt) ? __expf(e1 - mx) : 0.f;
    float den = p0 + p1;
#pragma unroll
    for (int off = 16; off; off >>= 1) den += __shfl_xor_sync(FULL, den, off);
    float inv = 1.f / fmaxf(den, 1e-30f);

    sw[h][lane]       = p0 * inv;
    sw[h][lane + 32]  = p1 * inv;
    scn[h][lane]      = c0;
    scn[h][lane + 32] = c1;
    __syncwarp();

    // unrolled gather: 4 independent chains for MLP
    float4 a0 = {0, 0, 0, 0}, a1 = {0, 0, 0, 0}, a2 = {0, 0, 0, 0}, a3 = {0, 0, 0, 0};
    const float* base = &g_Wh[(size_t)h * N_NODES * HID];
    int nit = (cnt + 3) & ~3;
    for (int jj = 0; jj < nit; jj += 4) {
        int ca = scn[h][jj], cb = scn[h][jj + 1], cc = scn[h][jj + 2], cd = scn[h][jj + 3];
        float wa = sw[h][jj], wb = sw[h][jj + 1], wc = sw[h][jj + 2], wd = sw[h][jj + 3];
        float4 va = *(const float4*)&base[(size_t)ca * HID + lane * 4];
        float4 vb = *(const float4*)&base[(size_t)cb * HID + lane * 4];
        float4 vc = *(const float4*)&base[(size_t)cc * HID + lane * 4];
        float4 vd = *(const float4*)&base[(size_t)cd * HID + lane * 4];
        a0.x += wa * va.x; a0.y += wa * va.y; a0.z += wa * va.z; a0.w += wa * va.w;
        a1.x += wb * vb.x; a1.y += wb * vb.y; a1.z += wb * vb.z; a1.w += wb * vb.w;
        a2.x += wc * vc.x; a2.y += wc * vc.y; a2.z += wc * vc.z; a2.w += wc * vc.w;
        a3.x += wd * vd.x; a3.y += wd * vd.y; a3.z += wd * vd.z; a3.w += wd * vd.w;
    }
    float o[4] = {a0.x + a1.x + a2.x + a3.x, a0.y + a1.y + a2.y + a3.y,
                  a0.z + a1.z + a2.z + a3.z, a0.w + a1.w + a2.w + a3.w};
#pragma unroll
    for (int t = 0; t < 4; ++t) {
        int f = lane * 4 + t;
        float sc = g1[f] * rsqrtf(v1[f] + EPS);
        float val = (o[t] - m1[f]) * sc + b1[f];
        o[t] = val > 0.f ? val : 0.f;
    }
    float4 ov = {o[0], o[1], o[2], o[3]};
    *(float4*)&g_xcat[(size_t)i * (NHEADS * HID) + h * HID + lane * 4] = ov;
}

// ---------------- K4: support = xcat @ gc_w (f32x2) ------------------------
__global__ __launch_bounds__(256) void k_support(const float* __restrict__ gcw) {
    __shared__ float As[64][65];
    __shared__ float Bs[64][40];
    int tid = threadIdx.x;
    int row = tid & 63;
    int cg = tid >> 6;                 // 4 groups of 10 classes
    int nodeBase = blockIdx.x * 64;
    unsigned long long acc[5];
#pragma unroll
    for (int c = 0; c < 5; ++c) acc[c] = 0ull;

    for (int kc = 0; kc < NHEADS * HID; kc += 64) {
        for (int f = tid; f < 64 * 64; f += 256) {
            int r = f >> 6, c = f & 63;
            As[r][c] = g_xcat[(size_t)(nodeBase + r) * (NHEADS * HID) + kc + c];
        }
        for (int f = tid; f < 64 * 40; f += 256) {
            int r = f / 40, c = f - r * 40;
            Bs[r][c] = gcw[(size_t)(kc + r) * NCLASS + c];
        }
        __syncthreads();
#pragma unroll 8
        for (int k = 0; k < 64; ++k) {
            float a = As[row][k];
            unsigned long long ap = pk2(a, a);
#pragma unroll
            for (int c = 0; c < 5; ++c) {
                unsigned long long bp = *(unsigned long long*)&Bs[k][cg * 10 + 2 * c];
                ffma2(acc[c], ap, bp);
            }
        }
        __syncthreads();
    }
#pragma unroll
    for (int c = 0; c < 5; ++c) {
        float lo, hi;
        upk2(acc[c], lo, hi);
        g_sup[(size_t)(nodeBase + row) * NCLASS + cg * 10 + 2 * c]     = lo;
        g_sup[(size_t)(nodeBase + row) * NCLASS + cg * 10 + 2 * c + 1] = hi;
    }
}

// ---------------- K5: residual smooth + bias + log_softmax -----------------
__global__ void k_final(const float* __restrict__ gcb, float* __restrict__ out) {
    __shared__ float sm[NCLASS];
    __shared__ float red[2];
    int i = blockIdx.x;
    int c = threadIdx.x;
    if (c < NCLASS) {
        float s = g_sup[(size_t)i * NCLASS + c];
        float acc = 0.f;
        int cnt = g_cnt[i];
        for (int jj = 0; jj < cnt; ++jj)
            acc += g_val[i * MAXD + jj] * g_sup[(size_t)g_col[i * MAXD + jj] * NCLASS + c];
        sm[c] = (0.5f * acc + s) * (1.f / 1.5f) + gcb[c];
    }
    __syncthreads();
    if (c == 0) {
        float mx = -INFINITY;
        for (int k = 0; k < NCLASS; ++k) mx = fmaxf(mx, sm[k]);
        float s = 0.f;
        for (int k = 0; k < NCLASS; ++k) s += __expf(sm[k] - mx);
        red[0] = mx; red[1] = logf(s);
    }
    __syncthreads();
    if (c < NCLASS) out[(size_t)i * NCLASS + c] = sm[c] - red[0] - red[1];
}

// ---------------- launch ----------------------------------------------------
extern "C" void kernel_launch(void* const* d_in, const int* in_sizes, int n_in,
                              void* d_out, int out_size) {
    const float* x     = (const float*)d_in[0];
    const float* adj   = (const float*)d_in[1];
    const float* Watt  = (const float*)d_in[2];
    const float* asrc  = (const float*)d_in[3];
    const float* adst  = (const float*)d_in[4];
    const float* bn0g  = (const float*)d_in[5];
    const float* bn0b  = (const float*)d_in[6];
    const float* bn0m  = (const float*)d_in[7];
    const float* bn0v  = (const float*)d_in[8];
    const float* bn1g  = (const float*)d_in[9];
    const float* bn1b  = (const float*)d_in[10];
    const float* bn1m  = (const float*)d_in[11];
    const float* bn1v  = (const float*)d_in[12];
    const float* gcw   = (const float*)d_in[13];
    const float* gcb   = (const float*)d_in[14];
    float* out = (float*)d_out;

    k_csr<<<N_NODES / 8, 256>>>(adj);
    k_wh<<<dim3(N_NODES / 128, NHEADS), 256>>>(x, Watt, asrc, adst,
                                               bn0g, bn0b, bn0m, bn0v);
    k_attn<<<N_NODES, 256>>>(bn1g, bn1b, bn1m, bn1v);
    k_support<<<N_NODES / 64, 256>>>(gcw);
    k_final<<<N_NODES, 64>>>(gcb, out);
}

// round 3
// speedup vs baseline: 1.4330x; 1.2095x over previous
#include <cuda_runtime.h>
#include <math.h>

#define N_NODES 6144
#define NFEAT   128
#define HID     128
#define NHEADS  8
#define NCLASS  40
#define MAXD    64
#define EPS     1e-5f
#define ALPHA   0.2f
#define FULL    0xffffffffu

// ---------------- scratch -------------------------------------------------
__device__ float g_Wh[NHEADS * N_NODES * HID];
__device__ float g_s1[NHEADS * N_NODES];
__device__ float g_s2[NHEADS * N_NODES];
__device__ int   g_col[N_NODES * MAXD];
__device__ float g_val[N_NODES * MAXD];
__device__ int   g_cnt[N_NODES];
__device__ float g_xcat[N_NODES * NHEADS * HID];
__device__ float g_sup[N_NODES * NCLASS];

// ---------------- packed f32x2 helpers ------------------------------------
__device__ __forceinline__ unsigned long long pk2(float lo, float hi) {
    unsigned long long r;
    asm("mov.b64 %0, {%1,%2};" : "=l"(r) : "f"(lo), "f"(hi));
    return r;
}
__device__ __forceinline__ void upk2(unsigned long long v, float& lo, float& hi) {
    asm("mov.b64 {%0,%1}, %2;" : "=f"(lo), "=f"(hi) : "l"(v));
}
__device__ __forceinline__ void ffma2(unsigned long long& d,
                                      unsigned long long a, unsigned long long b) {
    asm("fma.rn.f32x2 %0, %1, %2, %0;" : "+l"(d) : "l"(a), "l"(b));
}

// ---------------- K1: fused bn0 + Wh GEMM + score epilogue -----------------
__global__ __launch_bounds__(256) void k_wh(
    const float* __restrict__ x, const float* __restrict__ Watt,
    const float* __restrict__ asrc, const float* __restrict__ adst,
    const float* __restrict__ bg, const float* __restrict__ bb,
    const float* __restrict__ bm, const float* __restrict__ bv) {
    __shared__ float As[16][132];     // A transposed: As[k][node]
    __shared__ float Bs[16][128];
    __shared__ float s_sc[128], s_sh[128];
    int h = blockIdx.y;
    int nb = blockIdx.x * 128;
    int tid = threadIdx.x;
    int tc = tid & 15, tr = tid >> 4;

    if (tid < 128) {
        float s = bg[tid] * rsqrtf(bv[tid] + EPS);
        s_sc[tid] = s;
        s_sh[tid] = bb[tid] - bm[tid] * s;
    }
    unsigned long long acc[8][4];
#pragma unroll
    for (int r = 0; r < 8; ++r)
#pragma unroll
        for (int c = 0; c < 4; ++c) acc[r][c] = 0ull;
    __syncthreads();

    const float* Bg = Watt + (size_t)h * NFEAT * HID;
    for (int kc = 0; kc < NFEAT; kc += 16) {
#pragma unroll
        for (int l = 0; l < 2; ++l) {
            int f4 = tid + 256 * l;
            int r = f4 >> 2, cg = (f4 & 3) * 4;
            float4 v = *(const float4*)&x[(size_t)(nb + r) * NFEAT + kc + cg];
            As[cg + 0][r] = v.x * s_sc[kc + cg + 0] + s_sh[kc + cg + 0];
            As[cg + 1][r] = v.y * s_sc[kc + cg + 1] + s_sh[kc + cg + 1];
            As[cg + 2][r] = v.z * s_sc[kc + cg + 2] + s_sh[kc + cg + 2];
            As[cg + 3][r] = v.w * s_sc[kc + cg + 3] + s_sh[kc + cg + 3];
        }
#pragma unroll
        for (int l = 0; l < 2; ++l) {
            int f4 = tid + 256 * l;
            int r = f4 >> 5, c = (f4 & 31) * 4;
            *(float4*)&Bs[r][c] = *(const float4*)&Bg[(size_t)(kc + r) * HID + c];
        }
        __syncthreads();
#pragma unroll
        for (int k = 0; k < 16; ++k) {
            float4 a0 = *(float4*)&As[k][tr * 8];
            float4 a1 = *(float4*)&As[k][tr * 8 + 4];
            float4 bv0 = *(float4*)&Bs[k][tc * 8];
            float4 bv1 = *(float4*)&Bs[k][tc * 8 + 4];
            unsigned long long bp[4] = {pk2(bv0.x, bv0.y), pk2(bv0.z, bv0.w),
                                        pk2(bv1.x, bv1.y), pk2(bv1.z, bv1.w)};
            float ar[8] = {a0.x, a0.y, a0.z, a0.w, a1.x, a1.y, a1.z, a1.w};
#pragma unroll
            for (int r = 0; r < 8; ++r) {
                unsigned long long ap = pk2(ar[r], ar[r]);
#pragma unroll
                for (int c = 0; c < 4; ++c) ffma2(acc[r][c], ap, bp[c]);
            }
        }
        __syncthreads();
    }

    float accf[8][8];
#pragma unroll
    for (int r = 0; r < 8; ++r)
#pragma unroll
        for (int c = 0; c < 4; ++c) upk2(acc[r][c], accf[r][2 * c], accf[r][2 * c + 1]);

#pragma unroll
    for (int r = 0; r < 8; ++r) {
        int node = nb + tr * 8 + r;
        float4 o0 = {accf[r][0], accf[r][1], accf[r][2], accf[r][3]};
        float4 o1 = {accf[r][4], accf[r][5], accf[r][6], accf[r][7]};
        *(float4*)&g_Wh[((size_t)h * N_NODES + node) * HID + tc * 8]     = o0;
        *(float4*)&g_Wh[((size_t)h * N_NODES + node) * HID + tc * 8 + 4] = o1;
    }

    float av1[8], av2[8];
#pragma unroll
    for (int c = 0; c < 8; ++c) {
        av1[c] = asrc[h * HID + tc * 8 + c];
        av2[c] = adst[h * HID + tc * 8 + c];
    }
#pragma unroll
    for (int r = 0; r < 8; ++r) {
        float p1 = 0.f, p2 = 0.f;
#pragma unroll
        for (int c = 0; c < 8; ++c) { p1 += accf[r][c] * av1[c]; p2 += accf[r][c] * av2[c]; }
#pragma unroll
        for (int off = 8; off; off >>= 1) {
            p1 += __shfl_xor_sync(FULL, p1, off);
            p2 += __shfl_xor_sync(FULL, p2, off);
        }
        if (tc == 0) {
            int node = nb + tr * 8 + r;
            g_s1[h * N_NODES + node] = p1;
            g_s2[h * N_NODES + node] = p2;
        }
    }
}

// ---------------- K2: CSR build (warp/row, float4 loads) -------------------
__global__ void k_csr(const float* __restrict__ adj) {
    int row = (blockIdx.x * blockDim.x + threadIdx.x) >> 5;
    int lane = threadIdx.x & 31;
    if (row >= N_NODES) return;
    const float4* arow = (const float4*)(adj + (size_t)row * N_NODES);
    unsigned lt = (1u << lane) - 1u;
    int cnt = 0;
    for (int base = 0; base < N_NODES / 4; base += 32) {
        float4 v = arow[base + lane];
        float e[4] = {v.x, v.y, v.z, v.w};
#pragma unroll
        for (int j = 0; j < 4; ++j) {
            bool nz = e[j] > 0.f;
            unsigned msk = __ballot_sync(FULL, nz);
            int pos = cnt + __popc(msk & lt);
            if (nz && pos < MAXD) {
                g_col[row * MAXD + pos] = (base + lane) * 4 + j;
                g_val[row * MAXD + pos] = e[j];
            }
            cnt += __popc(msk);
        }
    }
    if (lane == 0) g_cnt[row] = cnt < MAXD ? cnt : MAXD;
}

// ---------------- K2b: zero g_sup ------------------------------------------
__global__ void k_zero() {
    int i = blockIdx.x * blockDim.x + threadIdx.x;
    if (i < N_NODES * NCLASS) g_sup[i] = 0.f;
}

// ---------------- K3: sparse attn softmax + aggregate + bn1 + relu ---------
__global__ __launch_bounds__(256) void k_attn(
    const float* __restrict__ g1, const float* __restrict__ b1,
    const float* __restrict__ m1, const float* __restrict__ v1) {
    __shared__ float sw[NHEADS][MAXD];
    __shared__ int   scn[NHEADS][MAXD];
    int i = blockIdx.x;
    int h = threadIdx.x >> 5;
    int lane = threadIdx.x & 31;
    int cnt = g_cnt[i];
    float s1i = g_s1[h * N_NODES + i];

    int   c0 = i, c1 = i;
    float e0 = -INFINITY, e1 = -INFINITY;
    if (lane < cnt) {
        c0 = g_col[i * MAXD + lane];
        float e = s1i + g_s2[h * N_NODES + c0];
        e0 = (e > 0.f) ? e : ALPHA * e;
    }
    if (lane + 32 < cnt) {
        c1 = g_col[i * MAXD + lane + 32];
        float e = s1i + g_s2[h * N_NODES + c1];
        e1 = (e > 0.f) ? e : ALPHA * e;
    }
    float mx = fmaxf(e0, e1);
#pragma unroll
    for (int off = 16; off; off >>= 1) mx = fmaxf(mx, __shfl_xor_sync(FULL, mx, off));
    float p0 = (lane < cnt)      ? __expf(e0 - mx) : 0.f;
    float p1 = (lane + 32 < cnt) ? __expf(e1 - mx) : 0.f;
    float den = p0 + p1;
#pragma unroll
    for (int off = 16; off; off >>= 1) den += __shfl_xor_sync(FULL, den, off);
    float inv = 1.f / fmaxf(den, 1e-30f);

    sw[h][lane]       = p0 * inv;
    sw[h][lane + 32]  = p1 * inv;
    scn[h][lane]      = c0;
    scn[h][lane + 32] = c1;
    __syncwarp();

    float4 a0 = {0, 0, 0, 0}, a1 = {0, 0, 0, 0}, a2 = {0, 0, 0, 0}, a3 = {0, 0, 0, 0};
    const float* base = &g_Wh[(size_t)h * N_NODES * HID];
    int nit = (cnt + 3) & ~3;
    for (int jj = 0; jj < nit; jj += 4) {
        int ca = scn[h][jj], cb = scn[h][jj + 1], cc = scn[h][jj + 2], cd = scn[h][jj + 3];
        float wa = sw[h][jj], wb = sw[h][jj + 1], wc = sw[h][jj + 2], wd = sw[h][jj + 3];
        float4 va = *(const float4*)&base[(size_t)ca * HID + lane * 4];
        float4 vb = *(const float4*)&base[(size_t)cb * HID + lane * 4];
        float4 vc = *(const float4*)&base[(size_t)cc * HID + lane * 4];
        float4 vd = *(const float4*)&base[(size_t)cd * HID + lane * 4];
        a0.x += wa * va.x; a0.y += wa * va.y; a0.z += wa * va.z; a0.w += wa * va.w;
        a1.x += wb * vb.x; a1.y += wb * vb.y; a1.z += wb * vb.z; a1.w += wb * vb.w;
        a2.x += wc * vc.x; a2.y += wc * vc.y; a2.z += wc * vc.z; a2.w += wc * vc.w;
        a3.x += wd * vd.x; a3.y += wd * vd.y; a3.z += wd * vd.z; a3.w += wd * vd.w;
    }
    float o[4] = {a0.x + a1.x + a2.x + a3.x, a0.y + a1.y + a2.y + a3.y,
                  a0.z + a1.z + a2.z + a3.z, a0.w + a1.w + a2.w + a3.w};
#pragma unroll
    for (int t = 0; t < 4; ++t) {
        int f = lane * 4 + t;
        float sc = g1[f] * rsqrtf(v1[f] + EPS);
        float val = (o[t] - m1[f]) * sc + b1[f];
        o[t] = val > 0.f ? val : 0.f;
    }
    float4 ov = {o[0], o[1], o[2], o[3]};
    *(float4*)&g_xcat[(size_t)i * (NHEADS * HID) + h * HID + lane * 4] = ov;
}

// ---------------- K4: support = xcat @ gc_w  (M-tile 128, K-split 8) -------
// grid = (48 node tiles, 8 k-splits), 256 threads.
// thread: 4 consecutive rows ((tid&31)*4) x 5 classes ((tid>>5)*5).
__global__ __launch_bounds__(256) void k_support(const float* __restrict__ gcw) {
    __shared__ float As[32][132];   // As[k][row], padded; LDS.128 over rows
    __shared__ float Bs[32][40];
    int tid = threadIdx.x;
    int nb = blockIdx.x * 128;
    int kbase = blockIdx.y * 128;   // this block's 128 K-values
    int rg = (tid & 31) * 4;        // first of 4 rows
    int cg = (tid >> 5) * 5;        // first of 5 classes

    unsigned long long acc[2][5];   // rows packed in pairs
#pragma unroll
    for (int p = 0; p < 2; ++p)
#pragma unroll
        for (int c = 0; c < 5; ++c) acc[p][c] = 0ull;

    for (int kc = 0; kc < 128; kc += 32) {
        // A: 32 k x 128 rows, transposed store. 1024 float4 loads.
#pragma unroll
        for (int rr = 0; rr < 4; ++rr) {
            int t = tid + rr * 256;
            int row = t >> 3;           // 0..127
            int kq = (t & 7) * 4;       // k offset 0..28
            float4 v = *(const float4*)&g_xcat[(size_t)(nb + row) * (NHEADS * HID)
                                               + kbase + kc + kq];
            As[kq + 0][row] = v.x;
            As[kq + 1][row] = v.y;
            As[kq + 2][row] = v.z;
            As[kq + 3][row] = v.w;
        }
        // B: 32 k x 40 classes = 1280 floats, coalesced linear.
#pragma unroll
        for (int l = 0; l < 5; ++l) {
            int f = tid + l * 256;
            ((float*)Bs)[ (f / 40) * 40 + (f % 40) ] = 0.f; // placate compiler aliasing
        }
        __syncthreads();   // (placeholder ordering; real fill below)
        // NOTE: fill Bs properly (overwrite) — gcw rows are contiguous so f maps linearly
#pragma unroll
        for (int l = 0; l < 5; ++l) {
            int f = tid + l * 256;
            int r = f / 40, c = f - r * 40;
            Bs[r][c] = gcw[(size_t)(kbase + kc + r) * NCLASS + c];
        }
        __syncthreads();
#pragma unroll
        for (int k = 0; k < 32; ++k) {
            float4 a4 = *(float4*)&As[k][rg];
            unsigned long long ap0 = pk2(a4.x, a4.y);
            unsigned long long ap1 = pk2(a4.z, a4.w);
#pragma unroll
            for (int c = 0; c < 5; ++c) {
                float b = Bs[k][cg + c];
                unsigned long long bp = pk2(b, b);
                ffma2(acc[0][c], ap0, bp);
                ffma2(acc[1][c], ap1, bp);
            }
        }
        __syncthreads();
    }
    // atomic accumulate partials
#pragma unroll
    for (int p = 0; p < 2; ++p)
#pragma unroll
        for (int c = 0; c < 5; ++c) {
            float lo, hi;
            upk2(acc[p][c], lo, hi);
            atomicAdd(&g_sup[(size_t)(nb + rg + 2 * p) * NCLASS + cg + c], lo);
            atomicAdd(&g_sup[(size_t)(nb + rg + 2 * p + 1) * NCLASS + cg + c], hi);
        }
}

// ---------------- K5: residual smooth + bias + log_softmax -----------------
__global__ void k_final(const float* __restrict__ gcb, float* __restrict__ out) {
    __shared__ float sm[NCLASS];
    __shared__ float red[2];
    int i = blockIdx.x;
    int c = threadIdx.x;
    if (c < NCLASS) {
        float s = g_sup[(size_t)i * NCLASS + c];
        float acc = 0.f;
        int cnt = g_cnt[i];
        for (int jj = 0; jj < cnt; ++jj)
            acc += g_val[i * MAXD + jj] * g_sup[(size_t)g_col[i * MAXD + jj] * NCLASS + c];
        sm[c] = (0.5f * acc + s) * (1.f / 1.5f) + gcb[c];
    }
    __syncthreads();
    if (c == 0) {
        float mx = -INFINITY;
        for (int k = 0; k < NCLASS; ++k) mx = fmaxf(mx, sm[k]);
        float s = 0.f;
        for (int k = 0; k < NCLASS; ++k) s += __expf(sm[k] - mx);
        red[0] = mx; red[1] = logf(s);
    }
    __syncthreads();
    if (c < NCLASS) out[(size_t)i * NCLASS + c] = sm[c] - red[0] - red[1];
}

// ---------------- launch ----------------------------------------------------
extern "C" void kernel_launch(void* const* d_in, const int* in_sizes, int n_in,
                              void* d_out, int out_size) {
    const float* x     = (const float*)d_in[0];
    const float* adj   = (const float*)d_in[1];
    const float* Watt  = (const float*)d_in[2];
    const float* asrc  = (const float*)d_in[3];
    const float* adst  = (const float*)d_in[4];
    const float* bn0g  = (const float*)d_in[5];
    const float* bn0b  = (const float*)d_in[6];
    const float* bn0m  = (const float*)d_in[7];
    const float* bn0v  = (const float*)d_in[8];
    const float* bn1g  = (const float*)d_in[9];
    const float* bn1b  = (const float*)d_in[10];
    const float* bn1m  = (const float*)d_in[11];
    const float* bn1v  = (const float*)d_in[12];
    const float* gcw   = (const float*)d_in[13];
    const float* gcb   = (const float*)d_in[14];
    float* out = (float*)d_out;

    k_csr<<<N_NODES / 8, 256>>>(adj);
    k_zero<<<(N_NODES * NCLASS + 255) / 256, 256>>>();
    k_wh<<<dim3(N_NODES / 128, NHEADS), 256>>>(x, Watt, asrc, adst,
                                               bn0g, bn0b, bn0m, bn0v);
    k_attn<<<N_NODES, 256>>>(bn1g, bn1b, bn1m, bn1v);
    k_support<<<dim3(N_NODES / 128, 8), 256>>>(gcw);
    k_final<<<N_NODES, 64>>>(gcb, out);
}